// round 13
// baseline (speedup 1.0000x reference)
#include <cuda_runtime.h>

// ExactWeightedDTM: B=4, H=W=64, N=4096, R=2, M0=0.01
//
// Identities (validated: rel_err ~1e-7):
//  - R=2 => dists_pow == d2 (integer 0..7938).
//  - Sort order is pure geometry => compile-time counting sort.
//  - Tie order within equal d2 is irrelevant.
//  - take = max(min(w, rem), 0); rem -= w, over d2-nondecreasing order matches
//    the reference clamped cumsum exactly; offsets past the stop contribute 0.
//
// R12 structure: THREAD-PER-PIXEL, LOCKSTEP TABLE WALK.
//  - warp = 32 consecutive x of one row; all lanes process the SAME offset
//    per iteration -> gather = 32 consecutive floats (coalesced L1 hits),
//    ZERO shuffles. Serial chain = one FADD (rem) per offset.
//  - block = 64 threads = one full row of one batch; 256 blocks, single wave.
//  - mass reduced in-block from the same loads that warm L1.
//  - table entry packs offset + d2-as-float: one LDG.64, uniform per warp.

#define NB        4
#define NPIX      4096
#define NBINS     8192
#define NOFF      16129                // 127*127
#define NOFF_PAD  16160                // multiple of 16 (and 32)
#define M0F       0.01f
#define FULL      0xFFFFFFFFu

struct __align__(8) Ent { unsigned p; float d2; };
struct Table { Ent e[NOFF_PAD]; };

// Compile-time d2-sorted table. p = ((dy+63)<<8) | (dx+63).
// Pad entries: dy+63 = 127 -> ny = y+64 always OOB.
constexpr Table make_table() {
    Table t{};
    int cnt[NBINS] = {};
    for (int dy = -63; dy <= 63; dy++)
        for (int dx = -63; dx <= 63; dx++)
            cnt[dy * dy + dx * dx]++;
    int pos[NBINS] = {};
    int run = 0;
    for (int b = 0; b < NBINS; b++) { pos[b] = run; run += cnt[b]; }
    for (int dy = -63; dy <= 63; dy++)
        for (int dx = -63; dx <= 63; dx++) {
            int d2 = dy * dy + dx * dx;
            t.e[pos[d2]].p  = ((unsigned)(dy + 63) << 8) | (unsigned)(dx + 63);
            t.e[pos[d2]].d2 = (float)d2;
            pos[d2]++;
        }
    for (int i = NOFF; i < NOFF_PAD; i++) { t.e[i].p = 0x7F7Fu; t.e[i].d2 = 0.f; }
    return t;
}

__device__ constexpr Table g_tab = make_table();

// ---------------------------------------------------------------------------
// Block = 64 threads = row y of batch b. Thread tid owns pixel (y, x=tid).
// ---------------------------------------------------------------------------
__global__ __launch_bounds__(64) void dtm_kernel(const float* __restrict__ img,
                                                 float* __restrict__ out) {
    __shared__ float s_red[2];

    const int tid  = threadIdx.x;              // 0..63 = x
    const int lane = tid & 31;
    const int b    = blockIdx.x >> 6;          // 64 blocks per batch
    const int y    = blockIdx.x & 63;

    const float* __restrict__ pb = img + b * NPIX;

    // ---- batch mass (also warms L1 with the whole image) ----
    const float4* v4 = (const float4*)pb;
    float sum = 0.f;
    #pragma unroll
    for (int i = 0; i < 16; i++) {
        float4 t = v4[tid + i * 64];
        sum += (t.x + t.y) + (t.z + t.w);
    }
    #pragma unroll
    for (int o = 16; o; o >>= 1) sum += __shfl_xor_sync(FULL, sum, o);
    if (lane == 0) s_red[tid >> 5] = sum;
    __syncthreads();
    const float mt = M0F * (s_red[0] + s_red[1]);

    float wsum = 0.f;

    if (mt > 0.f) {
        const int y63   = y - 63;
        const int x63   = tid - 63;
        const int cbase = (y63 << 6) + x63;     // + dyp*64 + dxp = ny*64+nx
        float rem = mt;

        for (int base = 0; base < NOFF_PAD; base += 16) {
            #pragma unroll
            for (int j = 0; j < 16; j++) {
                const Ent e = g_tab.e[base + j];        // uniform LDG.64
                const int dyp = (int)(e.p >> 8);
                const int dxp = (int)(e.p & 255u);
                const bool ok = ((unsigned)(y63 + dyp) < 64u) &
                                ((unsigned)(x63 + dxp) < 64u);
                float w = 0.f;
                if (ok)
                    w = __ldg(pb + cbase + (((int)e.p >> 2) & 0x3FC0) + dxp);
                float take = fmaxf(fminf(w, rem), 0.f);
                wsum = fmaf(take, e.d2, wsum);
                rem -= w;
            }
            if (__all_sync(FULL, rem <= 0.f)) break;    // warp-uniform exit
        }
    }

    out[b * NPIX + (y << 6) + tid] = (mt > 0.f) ? sqrtf(wsum / mt) : 0.f;
}

// ---------------------------------------------------------------------------
extern "C" void kernel_launch(void* const* d_in, const int* in_sizes, int n_in,
                              void* d_out, int out_size) {
    const float* img = (const float*)d_in[0];
    float*       out = (float*)d_out;

    dtm_kernel<<<256, 64>>>(img, out);   // 4 batches x 64 rows, single wave
}

// round 14
// speedup vs baseline: 1.8674x; 1.8674x over previous
#include <cuda_runtime.h>

// ExactWeightedDTM: B=4, H=W=64, N=4096, R=2, M0=0.01
//
// Identities (validated: rel_err ~1e-7):
//  - R=2 => dists_pow == d2 (integer 0..7938).
//  - Sort order is pure geometry => compile-time counting sort.
//  - Tie order within equal d2 is irrelevant.
//  - take = max(min(w, rem), 0); rem -= w, over d2-nondecreasing order matches
//    the reference clamped cumsum exactly; offsets past the stop contribute 0.
//
// R14 structure: LOCKSTEP THREAD-PER-PIXEL + SMEM-STAGED HOT LOOP.
//  - warp = 32 consecutive x of one row; all lanes share the table entry
//    (LDS broadcast), gather = 32 consecutive smem floats. Zero shuffles.
//  - block = 256 threads = 4 rows (g, g+16, g+32, g+48) of one batch;
//    64 blocks. 8 warps/block = 2/SMSP hides the short LDS stalls
//    (R12 lesson: 64-thread blocks left every chain exposed).
//  - image (16KB) + first 1024 table entries (8KB) staged cooperatively;
//    1024 entries = 6x margin over the worst corner pixel (~170 needed).
//    Global-table fallback kept for correctness.

#define NB        4
#define NPIX      4096
#define NBINS     8192
#define NOFF      16129                // 127*127
#define NOFF_PAD  16160                // multiple of 16
#define STAGE_N   1024                 // staged table entries (8 KB)
#define M0F       0.01f
#define FULL      0xFFFFFFFFu

struct __align__(8) Ent { unsigned p; float d2; };
struct Table { Ent e[NOFF_PAD]; };

// Compile-time d2-sorted table. p = ((dy+63)<<8) | (dx+63).
// Pad entries: dy+63 = 127 -> always OOB (w=0).
constexpr Table make_table() {
    Table t{};
    int cnt[NBINS] = {};
    for (int dy = -63; dy <= 63; dy++)
        for (int dx = -63; dx <= 63; dx++)
            cnt[dy * dy + dx * dx]++;
    int pos[NBINS] = {};
    int run = 0;
    for (int b = 0; b < NBINS; b++) { pos[b] = run; run += cnt[b]; }
    for (int dy = -63; dy <= 63; dy++)
        for (int dx = -63; dx <= 63; dx++) {
            int d2 = dy * dy + dx * dx;
            t.e[pos[d2]].p  = ((unsigned)(dy + 63) << 8) | (unsigned)(dx + 63);
            t.e[pos[d2]].d2 = (float)d2;
            pos[d2]++;
        }
    for (int i = NOFF; i < NOFF_PAD; i++) { t.e[i].p = 0x7F7Fu; t.e[i].d2 = 0.f; }
    return t;
}

__device__ constexpr Table g_tab = make_table();

// ---------------------------------------------------------------------------
__global__ __launch_bounds__(256) void dtm_kernel(const float* __restrict__ img,
                                                  float* __restrict__ out) {
    __shared__ float s_img[NPIX];        // 16 KB
    __shared__ Ent   s_tab[STAGE_N];     // 8 KB
    __shared__ float s_red[8];
    __shared__ float s_mt;

    const int tid  = threadIdx.x;                  // 0..255
    const int lane = tid & 31;
    const int wib  = tid >> 5;                     // 0..7
    const int b    = blockIdx.x >> 4;              // 16 blocks per batch
    const int g    = blockIdx.x & 15;
    const int y    = g + ((tid >> 6) << 4);        // rows g, g+16, g+32, g+48
    const int x    = tid & 63;

    // ---- stage image (float4) + accumulate mass; stage table (uint4) ----
    const float4* v4 = (const float4*)(img + b * NPIX);
    float4*       d4 = (float4*)s_img;
    float sum = 0.f;
    #pragma unroll
    for (int i = 0; i < 4; i++) {
        float4 t = v4[tid + i * 256];
        d4[tid + i * 256] = t;
        sum += (t.x + t.y) + (t.z + t.w);
    }
    {
        const uint4* ts = (const uint4*)g_tab.e;   // 2 entries per uint4
        uint4*       td = (uint4*)s_tab;
        #pragma unroll
        for (int i = 0; i < 2; i++) td[tid + i * 256] = ts[tid + i * 256];
    }
    #pragma unroll
    for (int o = 16; o; o >>= 1) sum += __shfl_xor_sync(FULL, sum, o);
    if (lane == 0) s_red[wib] = sum;
    __syncthreads();
    if (tid < 32) {
        float v = (tid < 8) ? s_red[tid] : 0.f;
        #pragma unroll
        for (int o = 4; o; o >>= 1) v += __shfl_xor_sync(FULL, v, o);
        if (tid == 0) s_mt = M0F * v;
    }
    __syncthreads();
    const float mt = s_mt;

    float wsum = 0.f;

    if (mt > 0.f) {
        const int y63 = y - 63;
        const int x63 = x - 63;
        const int cbase = (y63 << 6) + x63;        // + dyp*64 + dxp = ny*64+nx
        float rem = mt;
        bool done = false;

        // ---- staged hot loop: LDS broadcast table + LDS gather ----
        for (int base = 0; base < STAGE_N; base += 16) {
            #pragma unroll
            for (int j = 0; j < 16; j++) {
                const Ent e  = s_tab[base + j];
                const int dyp = (int)(e.p >> 8);
                const int dxp = (int)(e.p & 255u);
                const bool ok = ((unsigned)(y63 + dyp) < 64u) &
                                ((unsigned)(x63 + dxp) < 64u);
                float w = 0.f;
                if (ok) w = s_img[cbase + (dyp << 6) + dxp];
                const float take = fmaxf(fminf(w, rem), 0.f);
                wsum = fmaf(take, e.d2, wsum);
                rem -= w;
            }
            if (__all_sync(FULL, rem <= 0.f)) { done = true; break; }
        }

        // ---- fallback (statistically never taken; correctness guard) ----
        if (!done) {
            for (int base = STAGE_N; base < NOFF_PAD; base += 16) {
                #pragma unroll
                for (int j = 0; j < 16; j++) {
                    const Ent e  = g_tab.e[base + j];
                    const int dyp = (int)(e.p >> 8);
                    const int dxp = (int)(e.p & 255u);
                    const bool ok = ((unsigned)(y63 + dyp) < 64u) &
                                    ((unsigned)(x63 + dxp) < 64u);
                    float w = 0.f;
                    if (ok) w = s_img[cbase + (dyp << 6) + dxp];
                    const float take = fmaxf(fminf(w, rem), 0.f);
                    wsum = fmaf(take, e.d2, wsum);
                    rem -= w;
                }
                if (__all_sync(FULL, rem <= 0.f)) break;
            }
        }
    }

    out[b * NPIX + (y << 6) + x] = (mt > 0.f) ? sqrtf(wsum / mt) : 0.f;
}

// ---------------------------------------------------------------------------
extern "C" void kernel_launch(void* const* d_in, const int* in_sizes, int n_in,
                              void* d_out, int out_size) {
    const float* img = (const float*)d_in[0];
    float*       out = (float*)d_out;

    dtm_kernel<<<64, 256>>>(img, out);   // 4 batches x 16 blocks x 4 rows
}